// round 6
// baseline (speedup 1.0000x reference)
#include <cuda_runtime.h>
#include <math.h>
#include <float.h>

#define B 8
#define H 480
#define W 640
#define HW (H*W)
#define TOPK 500
#define NKP (B*TOPK)
#define CAP 131072

#define KXY_OFF 0
#define DESC_OFF (NKP*2)
#define KPS_OFF (DESC_OFF + NKP*64)
#define DISP_OFF (KPS_OFF + NKP)

// ---------------- device scratch ----------------
__device__ float g_cval[B*CAP];
__device__ int   g_cidx[B*CAP];
__device__ int   g_cnt[B];          // zero at load; re-zeroed by select (replay-safe)
__device__ int   g_topk[NKP];

// ============================================================================
// Fused NMS: 64x32 output tile, radius-10 halo. 52 rows x PW=92 padded cols.
// Data cols sc in [4,88); guards zero. Masks bit-packed: 4 uints per row
// (bit sc of word sc>>5). Max-passes fused (h-max in regs + v-max sliding).
// ============================================================================
#define PW 92

#define F4(A, r, cb)   (*(const float4*)&A[(r)*PW + (cb)])

__device__ __forceinline__ float4 f4max(float4 a, float4 b) {
    return make_float4(fmaxf(a.x,b.x), fmaxf(a.y,b.y), fmaxf(a.z,b.z), fmaxf(a.w,b.w));
}
__device__ __forceinline__ float fmax5(float a, float b, float c, float d, float e) {
    return fmaxf(fmaxf(fmaxf(a, b), fmaxf(c, d)), e);
}
// zero out lanes whose bit (0..3) is set
__device__ __forceinline__ float4 mask4(float4 t, unsigned bits) {
    t.x = (bits & 1u) ? 0.f : t.x;
    t.y = (bits & 2u) ? 0.f : t.y;
    t.z = (bits & 4u) ? 0.f : t.z;
    t.w = (bits & 8u) ? 0.f : t.w;
    return t;
}

__global__ __launch_bounds__(256) void nms_kernel(const float* __restrict__ s) {
    __shared__ __align__(16) float sT[52*PW];
    __shared__ unsigned Mb  [52*4];   // max mask bits
    __shared__ unsigned SMKb[52*4];   // suppression mask bits
    __shared__ unsigned TUb [52*4];   // vertical-OR temp

    int b = blockIdx.z, tid = threadIdx.x;
    int gx0 = blockIdx.x*64 - 10, gy0 = blockIdx.y*32 - 10;
    const float* sp = s + (size_t)b*HW;

    for (int i = tid; i < 52*4; i += 256) { Mb[i] = 0u; SMKb[i] = 0u; TUb[i] = 0u; }
    for (int i = tid; i < 52*PW; i += 256) {
        int r = i / PW, sc = i - r*PW;
        int gy = gy0 + r, gx = gx0 + sc - 4;
        float v = 0.f;
        if (sc >= 4 && sc < 88 && gy >= 0 && gy < H && gx >= 0 && gx < W)
            v = sp[gy*W + gx];
        sT[i] = v;
    }
    __syncthreads();

    // ---- stage 1: strict local max of raw scores, rows [2,50) ----
    // item: chunk k (cb=4+4k, 21 chunks) x row-group g (4 rows) -> 12*21=252
    for (int i = tid; i < 12*21; i += 256) {
        int g = i/21, k = i - g*21;
        int r0 = 2 + 4*g, cb = 4 + 4*k;
        float4 h[8];
        #pragma unroll
        for (int j = 0; j < 8; j++) {
            int rr = r0 - 2 + j;
            float4 L = F4(sT,rr,cb-4), Md = F4(sT,rr,cb), R = F4(sT,rr,cb+4);
            h[j].x = fmax5(L.z, L.w, Md.x, Md.y, Md.z);
            h[j].y = fmax5(L.w, Md.x, Md.y, Md.z, Md.w);
            h[j].z = fmax5(Md.x, Md.y, Md.z, Md.w, R.x);
            h[j].w = fmax5(Md.y, Md.z, Md.w, R.x, R.y);
        }
        #pragma unroll
        for (int j = 0; j < 4; j++) {
            float4 vm = f4max(f4max(f4max(h[j],h[j+1]), f4max(h[j+2],h[j+3])), h[j+4]);
            float4 t = F4(sT, r0+j, cb);
            unsigned bits = (t.x==vm.x ? 1u:0u) | (t.y==vm.y ? 2u:0u)
                          | (t.z==vm.z ? 4u:0u) | (t.w==vm.w ? 8u:0u);
            if (bits) atomicOr(&Mb[(r0+j)*4 + (cb>>5)], bits << (cb & 31));
        }
    }
    __syncthreads();

    // suppression-mask passes (bit-packed). A: vertical OR5; B: horizontal OR5.
#define SUPP_A(R0, NR)                                                        \
    for (int i = tid; i < (NR)*3; i += 256) {                                 \
        int r = (R0) + i/3, w = i - (i/3)*3;                                  \
        TUb[r*4+w] = Mb[(r-2)*4+w] | Mb[(r-1)*4+w] | Mb[r*4+w]                \
                   | Mb[(r+1)*4+w] | Mb[(r+2)*4+w];                           \
    }
#define SUPP_B(R0, NR)                                                        \
    for (int i = tid; i < (NR)*3; i += 256) {                                 \
        int r = (R0) + i/3, w = i - (i/3)*3;                                  \
        unsigned t = TUb[r*4+w];                                              \
        unsigned tl = w ? TUb[r*4+w-1] : 0u;                                  \
        unsigned tr = TUb[r*4+w+1];                                           \
        SMKb[r*4+w] = t | __funnelshift_l(tl,t,1) | __funnelshift_l(tl,t,2)   \
                        | __funnelshift_r(t,tr,1) | __funnelshift_r(t,tr,2);  \
    }

    // ---- stage 2: SMK from M, rows [4,48) ----
    SUPP_A(4, 44)
    __syncthreads();
    SUPP_B(4, 44)
    __syncthreads();

    // ---- stage 3: M |= (SS == max5(SS)) & !SMK, rows [6,46) ----
    for (int i = tid; i < 10*21; i += 256) {
        int g = i/21, k = i - g*21;
        int r0 = 6 + 4*g, cb = 4 + 4*k;
        int q = (cb-4) >> 5, off = (cb-4) & 31;
        float4 h[8], ctr[4];
        unsigned wv[4];
        #pragma unroll
        for (int j = 0; j < 8; j++) {
            int rr = r0 - 2 + j;
            unsigned win = __funnelshift_r(SMKb[rr*4+q], SMKb[rr*4+q+1], off);
            float4 L  = mask4(F4(sT,rr,cb-4), win & 0xFu);
            float4 Md = mask4(F4(sT,rr,cb), (win>>4) & 0xFu);
            float4 R  = mask4(F4(sT,rr,cb+4), (win>>8) & 0xFu);
            h[j].x = fmax5(L.z, L.w, Md.x, Md.y, Md.z);
            h[j].y = fmax5(L.w, Md.x, Md.y, Md.z, Md.w);
            h[j].z = fmax5(Md.x, Md.y, Md.z, Md.w, R.x);
            h[j].w = fmax5(Md.y, Md.z, Md.w, R.x, R.y);
            if (j >= 2 && j < 6) { ctr[j-2] = Md; wv[j-2] = win; }
        }
        #pragma unroll
        for (int j = 0; j < 4; j++) {
            float4 vm = f4max(f4max(f4max(h[j],h[j+1]), f4max(h[j+2],h[j+3])), h[j+4]);
            float4 t = ctr[j];
            unsigned smk = (wv[j] >> 4) & 0xFu;
            unsigned bits = ((t.x==vm.x && !(smk&1u)) ? 1u:0u)
                          | ((t.y==vm.y && !(smk&2u)) ? 2u:0u)
                          | ((t.z==vm.z && !(smk&4u)) ? 4u:0u)
                          | ((t.w==vm.w && !(smk&8u)) ? 8u:0u);
            if (bits) atomicOr(&Mb[(r0+j)*4 + (cb>>5)], bits << (cb & 31));
        }
    }
    __syncthreads();

    // ---- stage 4: SMK from updated M, rows [8,44) ----
    SUPP_A(8, 36)
    __syncthreads();
    SUPP_B(8, 36)
    __syncthreads();

    // ---- stage 5 + border + compaction: rows [10,42), out cols sc [14,78) ----
    for (int i = tid; i < 8*17; i += 256) {
        int g = i/17, k = i - g*17;
        int r0 = 10 + 4*g, cb = 12 + 4*k;
        int q = (cb-4) >> 5, off = (cb-4) & 31;
        float4 h[8], ctr[4];
        unsigned wv[4];
        #pragma unroll
        for (int j = 0; j < 8; j++) {
            int rr = r0 - 2 + j;
            unsigned win = __funnelshift_r(SMKb[rr*4+q], SMKb[rr*4+q+1], off);
            float4 L  = mask4(F4(sT,rr,cb-4), win & 0xFu);
            float4 Md = mask4(F4(sT,rr,cb), (win>>4) & 0xFu);
            float4 R  = mask4(F4(sT,rr,cb+4), (win>>8) & 0xFu);
            h[j].x = fmax5(L.z, L.w, Md.x, Md.y, Md.z);
            h[j].y = fmax5(L.w, Md.x, Md.y, Md.z, Md.w);
            h[j].z = fmax5(Md.x, Md.y, Md.z, Md.w, R.x);
            h[j].w = fmax5(Md.y, Md.z, Md.w, R.x, R.y);
            if (j >= 2 && j < 6) { ctr[j-2] = Md; wv[j-2] = win; }
        }
        #pragma unroll
        for (int j = 0; j < 4; j++) {
            float4 vm = f4max(f4max(f4max(h[j],h[j+1]), f4max(h[j+2],h[j+3])), h[j+4]);
            float4 t = ctr[j];
            unsigned smk = (wv[j] >> 4) & 0xFu;
            int r = r0 + j;
            unsigned mwin = __funnelshift_r(Mb[r*4+q], Mb[r*4+q+1], off);
            unsigned fin = ((mwin >> 4) & 0xFu)
                         | ((t.x==vm.x && !(smk&1u)) ? 1u:0u)
                         | ((t.y==vm.y && !(smk&2u)) ? 2u:0u)
                         | ((t.z==vm.z && !(smk&4u)) ? 4u:0u)
                         | ((t.w==vm.w && !(smk&8u)) ? 8u:0u);
            if (fin) {
                #pragma unroll
                for (int jj = 0; jj < 4; jj++) {
                    if ((fin >> jj) & 1u) {
                        int sc = cb + jj;
                        if (sc >= 14 && sc < 78) {
                            int gy = gy0 + r, gx = gx0 + sc - 4;
                            if (gy >= 3 && gy < H-2 && gx >= 3 && gx < W-2) {
                                int pos = atomicAdd(&g_cnt[b], 1);
                                if (pos < CAP) {
                                    g_cval[b*CAP + pos] = sT[r*PW + sc];
                                    g_cidx[b*CAP + pos] = gy*W + gx;
                                }
                            }
                        }
                    }
                }
            }
        }
    }
}

// ============================================================================
// per-batch top-500: 3-level radix threshold + rank placement; re-zeroes g_cnt
// ============================================================================
__global__ __launch_bounds__(1024) void select_kernel() {
    __shared__ unsigned hist[2048];
    __shared__ unsigned gsum[64];
    __shared__ unsigned sel_key[1024];
    __shared__ int      sel_idx[1024];
    __shared__ int s_bsel, s_need, s_cnt;

    int b = blockIdx.x, tid = threadIdx.x;
    int lane = tid & 31, wid = tid >> 5;
    int n = min(g_cnt[b], CAP);
    __syncthreads();                     // all reads of g_cnt[b] complete ...
    if (tid == 0) g_cnt[b] = 0;          // ... before the reset (replay-safe)
    const float* vals = g_cval + b*CAP;
    const int*   idxs = g_cidx + b*CAP;

    unsigned prefix = 0;
    int need = TOPK;
    for (int level = 0; level < 3; level++) {
        int nbins = (level == 2) ? 1024 : 2048;
        for (int i = tid; i < nbins; i += 1024) hist[i] = 0;
        __syncthreads();
        for (int i = tid; i < n; i += 1024) {
            unsigned key = __float_as_uint(vals[i]);
            unsigned bin; bool ok;
            if (level == 0)      { ok = true;                  bin = key >> 21; }
            else if (level == 1) { ok = (key >> 21) == prefix; bin = (key >> 10) & 0x7FF; }
            else                 { ok = (key >> 10) == prefix; bin = key & 0x3FF; }
            if (ok) atomicAdd(&hist[bin], 1);
        }
        __syncthreads();
        {
            unsigned v = hist[tid];
            #pragma unroll
            for (int o = 16; o > 0; o >>= 1) v += __shfl_down_sync(~0u, v, o);
            if (lane == 0) gsum[wid] = v;
            if (nbins == 2048) {
                unsigned v2 = hist[tid + 1024];
                #pragma unroll
                for (int o = 16; o > 0; o >>= 1) v2 += __shfl_down_sync(~0u, v2, o);
                if (lane == 0) gsum[32 + wid] = v2;
            }
        }
        __syncthreads();
        if (wid == 0) {
            int ng = nbins >> 5;
            unsigned g0 = gsum[lane];
            unsigned g1 = (ng == 64) ? gsum[32 + lane] : 0u;
            unsigned s1 = g1;
            #pragma unroll
            for (int o = 1; o < 32; o <<= 1) { unsigned t = __shfl_down_sync(~0u, s1, o); if (lane + o < 32) s1 += t; }
            unsigned tot1 = __shfl_sync(~0u, s1, 0);
            unsigned s0 = g0;
            #pragma unroll
            for (int o = 1; o < 32; o <<= 1) { unsigned t = __shfl_down_sync(~0u, s0, o); if (lane + o < 32) s0 += t; }
            s0 += tot1;
            unsigned b0 = __ballot_sync(~0u, s0 >= (unsigned)need);
            unsigned b1 = __ballot_sync(~0u, (ng == 64) && (s1 >= (unsigned)need));
            int gstar; unsigned suf_after;
            if (b1) {
                int j = 31 - __clz(b1);
                gstar = 32 + j;
                suf_after = (j == 31) ? 0u : __shfl_sync(~0u, s1, j + 1);
            } else {
                gstar = 31 - __clz(b0);
                suf_after = (gstar == 31) ? tot1 : __shfl_sync(~0u, s0, gstar + 1);
            }
            int need_g = need - (int)suf_after;
            unsigned hs = hist[gstar*32 + lane];
            #pragma unroll
            for (int o = 1; o < 32; o <<= 1) { unsigned t = __shfl_down_sync(~0u, hs, o); if (lane + o < 32) hs += t; }
            unsigned bb = __ballot_sync(~0u, hs >= (unsigned)need_g);
            int bstar = 31 - __clz(bb);
            unsigned bsuf = (bstar == 31) ? 0u : __shfl_sync(~0u, hs, bstar + 1);
            if (lane == 0) { s_bsel = gstar*32 + bstar; s_need = need_g - (int)bsuf; }
        }
        __syncthreads();
        if (level == 0)      prefix = (unsigned)s_bsel;
        else if (level == 1) prefix = (prefix << 11) | (unsigned)s_bsel;
        else                 prefix = (prefix << 10) | (unsigned)s_bsel;
        need = s_need;
        __syncthreads();
    }
    unsigned T = prefix;

    if (tid == 0) s_cnt = 0;
    __syncthreads();
    for (int i = tid; i < n; i += 1024) {
        unsigned key = __float_as_uint(vals[i]);
        if (key >= T) {
            int p = atomicAdd(&s_cnt, 1);
            if (p < 1024) { sel_key[p] = key; sel_idx[p] = idxs[i]; }
        }
    }
    __syncthreads();
    int cnt = min(s_cnt, 1024);
    if (tid < cnt) {
        unsigned ki = sel_key[tid];
        int ii = sel_idx[tid];
        int rank = 0;
        for (int j = 0; j < cnt; j++) {
            unsigned kj = sel_key[j];
            int ij = sel_idx[j];
            rank += (kj > ki) || (kj == ki && ij < ii);
        }
        if (rank < TOPK) g_topk[b*TOPK + rank] = ii;
    }
}

__device__ __forceinline__ float wmax(float v) {
    #pragma unroll
    for (int o = 16; o > 0; o >>= 1) v = fmaxf(v, __shfl_xor_sync(0xffffffffu, v, o));
    return v;
}

// ============================================================================
// fused patch refinement + descriptor sampling: 8 keypoints per 512-thr block
// ============================================================================
__global__ __launch_bounds__(512) void patch_desc_kernel(
        const float* __restrict__ s, const float* __restrict__ dmap,
        float* __restrict__ out) {
    __shared__ float spx[8], spy[8];
    __shared__ float part[16];
    int tid = threadIdx.x;
    int kbase = blockIdx.x * 8;
    int wid = tid >> 5, lane = tid & 31;

    // ---- phase 1: warps 0..7 each refine one keypoint ----
    if (wid < 8) {
        int gw = kbase + wid;
        int b = gw / TOPK;
        int p = g_topk[gw];
        int y = p / W, x = p - y*W;
        int ky = lane / 5, kx = lane - ky*5;
        float v = -FLT_MAX;
        if (lane < 25) v = s[(size_t)b*HW + (y + ky - 2)*W + (x + kx - 2)];
        float mx = wmax(v);
        float gxk = (float)(kx - 2), gyk = (float)(ky - 2);
        float e = (lane < 25) ? __expf((v - mx) * 10.f) : 0.f;
        float s0 = e, s1 = e*gxk, s2 = e*gyk, s3 = e*(gxk*gxk + gyk*gyk);
        #pragma unroll
        for (int o = 16; o > 0; o >>= 1) {
            s0 += __shfl_xor_sync(~0u, s0, o);
            s1 += __shfl_xor_sync(~0u, s1, o);
            s2 += __shfl_xor_sync(~0u, s2, o);
            s3 += __shfl_xor_sync(~0u, s3, o);
        }
        if (lane == 0) {
            float denom = s0 + 1e-12f;
            float inv = 1.f / denom;
            float xr = s1 * inv, yr = s2 * inv;
            float disp = (s3 - 2.f*xr*s1 - 2.f*yr*s2 + (xr*xr + yr*yr)*s0) * 0.25f * inv;
            float fx = (float)x + xr, fy = (float)y + yr;
            float gx = fx / (float)(W-1) * 2.f - 1.f;
            float gy = fy / (float)(H-1) * 2.f - 1.f;
            out[KXY_OFF + gw*2 + 0] = gx;
            out[KXY_OFF + gw*2 + 1] = gy;
            out[DISP_OFF + gw] = disp;

            float px = fminf(fmaxf((gx + 1.f) * 0.5f * (float)(W-1), 0.f), (float)(W-1));
            float py = fminf(fmaxf((gy + 1.f) * 0.5f * (float)(H-1), 0.f), (float)(H-1));
            spx[wid] = px; spy[wid] = py;
            int x0 = (int)floorf(px), y0 = (int)floorf(py);
            float wx = px - (float)x0, wy = py - (float)y0;
            int x1 = min(x0 + 1, W-1), y1 = min(y0 + 1, H-1);
            const float* sb = s + (size_t)b*HW;
            float v00 = sb[y0*W + x0], v01 = sb[y0*W + x1];
            float v10 = sb[y1*W + x0], v11 = sb[y1*W + x1];
            out[KPS_OFF + gw] = v00*(1.f-wx)*(1.f-wy) + v01*wx*(1.f-wy)
                              + v10*(1.f-wx)*wy       + v11*wx*wy;
        }
    }
    __syncthreads();

    // ---- phase 2: descriptor gather + L2 norm (64 threads / keypoint) ----
    int kl = tid >> 6;            // 0..7
    int c  = tid & 63;
    int g  = kbase + kl;
    int b  = g / TOPK;
    float px = spx[kl], py = spy[kl];
    int x0 = (int)floorf(px), y0 = (int)floorf(py);
    float wx = px - (float)x0, wy = py - (float)y0;
    int x1 = min(x0 + 1, W-1), y1 = min(y0 + 1, H-1);
    const float* base = dmap + ((size_t)b*64 + c) * (size_t)HW;
    float v00 = base[y0*W + x0], v01 = base[y0*W + x1];
    float v10 = base[y1*W + x0], v11 = base[y1*W + x1];
    float d = v00*(1.f-wx)*(1.f-wy) + v01*wx*(1.f-wy)
            + v10*(1.f-wx)*wy       + v11*wx*wy;

    float ss = d * d;
    #pragma unroll
    for (int o = 16; o > 0; o >>= 1) ss += __shfl_xor_sync(0xffffffffu, ss, o);
    if (lane == 0) part[wid] = ss;
    __syncthreads();
    float tot = part[2*kl] + part[2*kl + 1];
    float nrm = fmaxf(sqrtf(tot), 1e-12f);
    out[DESC_OFF + g*64 + c] = d / nrm;
}

extern "C" void kernel_launch(void* const* d_in, const int* in_sizes, int n_in,
                              void* d_out, int out_size) {
    const float* scores = (const float*)d_in[0];
    const float* descs  = (const float*)d_in[1];
    float* out = (float*)d_out;

    nms_kernel<<<dim3(W/64, H/32, B), 256>>>(scores);
    select_kernel<<<B, 1024>>>();
    patch_desc_kernel<<<NKP/8, 512>>>(scores, descs, out);
}